// round 9
// baseline (speedup 1.0000x reference)
#include <cuda_runtime.h>
#include <cuda_bf16.h>

#define NB 296
#define NTILE 256
#define DIMK 128
#define TPX 68
#define CSHIFT 100.0f

typedef unsigned long long ull;

// ---- scratch globals (allocation-free; all state self-resets across replays) ----
__device__ float    g_d[1024 * 1024];      // distance matrix (4MB, L2-resident)
__device__ float    g_rpart[1024 * 16];    // row sumexp partials [row][tile_bx]
__device__ float    g_cpart[1024 * 16];    // col sumexp partials [col][tile_by]
__device__ float    g_rinv[1024];
__device__ float    g_cinv[1024];
__device__ float    g_P1[NB], g_P2[NB];
__device__ unsigned g_ticket;              // reset by bar-0 releaser
__device__ unsigned g_done;                // reset by last block
__device__ unsigned g_cnt[2];              // barrier arrivals (self-reset)
__device__ unsigned g_gen[2];              // barrier generations (monotonic)

// ---- packed f32x2 helpers ----
__device__ __forceinline__ ull fma2_(ull a, ull b, ull c) {
    ull d; asm("fma.rn.f32x2 %0, %1, %2, %3;" : "=l"(d) : "l"(a), "l"(b), "l"(c)); return d;
}
__device__ __forceinline__ ull add2_(ull a, ull b) {
    ull d; asm("add.rn.f32x2 %0, %1, %2;" : "=l"(d) : "l"(a), "l"(b)); return d;
}
__device__ __forceinline__ float lo_(ull v) { return __uint_as_float((unsigned)(v & 0xFFFFFFFFu)); }
__device__ __forceinline__ float hi_(ull v) { return __uint_as_float((unsigned)(v >> 32)); }

#define NEG1_2 0xBF800000BF800000ULL
#define ABS2   0x7FFFFFFF7FFFFFFFULL

__device__ __forceinline__ float warp_sum(float v) {
#pragma unroll
    for (int o = 16; o > 0; o >>= 1) v += __shfl_xor_sync(0xFFFFFFFFu, v, o);
    return v;
}

__device__ __forceinline__ void grid_bar(int i, bool reset_ticket) {
    __syncthreads();
    if (threadIdx.x == 0) {
        volatile unsigned* genp = (volatile unsigned*)&g_gen[i];
        unsigned start = *genp;
        __threadfence();
        unsigned my = atomicAdd(&g_cnt[i], 1u);
        if (my == NB - 1) {
            g_cnt[i] = 0;
            if (reset_ticket) g_ticket = 0;
            __threadfence();
            atomicAdd(&g_gen[i], 1u);
        } else {
            while (*genp == start) { }
            __threadfence();
        }
    }
    __syncthreads();
}

// ---------------------------------------------------------------- the kernel
// 296 persistent blocks x 512 threads; 256 dynamic 64x64 tiles; micro 2x4.
__global__ __launch_bounds__(512, 2)
void k_all(const float* __restrict__ zx, const float* __restrict__ zy,
           const float* __restrict__ theta, const float* __restrict__ beta,
           float* __restrict__ out, int nout) {
    __shared__ float SH[2 * 64 * TPX];
    __shared__ float s_aux[40];
    __shared__ unsigned s_t;
    float* xs = SH;
    float* ys = SH + 64 * TPX;

    const int tid  = threadIdx.x;
    const int lane = tid & 31, w = tid >> 5;
    const int tx   = tid & 15;                 // cols 4tx..4tx+3
    const int ty   = tid >> 4;                 // rows 2ty..2ty+1
    const int bid  = blockIdx.x;

    const int row0 = 2 * ty, row1 = 2 * ty + 1;
    const int k0 = (row0 >> 2) & 15, k1 = (row1 >> 2) & 15;

    // ================= Phase 1: dynamic tiles: dist + exp + partials =================
    while (true) {
        __syncthreads();                       // protect s_t and smem reuse
        if (tid == 0) s_t = atomicAdd(&g_ticket, 1u);
        __syncthreads();
        unsigned tt = s_t;
        if (tt >= NTILE) break;

        const int bx = tt & 15, by = tt >> 4;
        const int bi = by << 6, bj = bx << 6;

        ull acc[2][4];
#pragma unroll
        for (int i = 0; i < 2; i++)
#pragma unroll
            for (int j = 0; j < 4; j++) acc[i][j] = 0ULL;

        for (int kc = 0; kc < 2; kc++) {
            if (kc) __syncthreads();
#pragma unroll
            for (int l = tid; l < 1024; l += 512) {
                int r  = l >> 4;
                int dq = l & 15;
                int sw = (dq ^ ((r >> 2) & 15)) << 2;
                float4 vx = *reinterpret_cast<const float4*>(zx + (bi + r) * DIMK + kc * 64 + dq * 4);
                *reinterpret_cast<float4*>(&xs[r * TPX + sw]) = vx;
                float4 vy = *reinterpret_cast<const float4*>(zy + (bj + r) * DIMK + kc * 64 + dq * 4);
                *reinterpret_cast<float4*>(&ys[r * TPX + sw]) = vy;
            }
            __syncthreads();

#pragma unroll 4
            for (int dq = 0; dq < 16; dq++) {
                ulonglong2 av[2], bv[4];
                av[0] = *reinterpret_cast<const ulonglong2*>(&xs[row0 * TPX + ((dq ^ k0) << 2)]);
                av[1] = *reinterpret_cast<const ulonglong2*>(&xs[row1 * TPX + ((dq ^ k1) << 2)]);
                int gy = (dq ^ tx) << 2;
#pragma unroll
                for (int jj = 0; jj < 4; jj++)
                    bv[jj] = *reinterpret_cast<const ulonglong2*>(&ys[(4 * tx + jj) * TPX + gy]);
#pragma unroll
                for (int ii = 0; ii < 2; ii++)
#pragma unroll
                    for (int jj = 0; jj < 4; jj++) {
                        ull d0 = fma2_(bv[jj].x, NEG1_2, av[ii].x) & ABS2;
                        ull d1 = fma2_(bv[jj].y, NEG1_2, av[ii].y) & ABS2;
                        acc[ii][jj] = add2_(acc[ii][jj], add2_(d0, d1));
                    }
            }
        }

        // collapse packed pairs; exp with constant shift; write d-tile
        float accv[2][4], e[2][4];
#pragma unroll
        for (int ii = 0; ii < 2; ii++) {
#pragma unroll
            for (int jj = 0; jj < 4; jj++) {
                float a = lo_(acc[ii][jj]) + hi_(acc[ii][jj]);
                accv[ii][jj] = a;
                e[ii][jj] = __expf(CSHIFT - a);
            }
            *reinterpret_cast<float4*>(&g_d[(bi + 2 * ty + ii) * 1024 + bj + 4 * tx]) =
                make_float4(accv[ii][0], accv[ii][1], accv[ii][2], accv[ii][3]);
        }

        // row partials (reduce over 16 tx-lanes within half-warp)
#pragma unroll
        for (int ii = 0; ii < 2; ii++) {
            float r = (e[ii][0] + e[ii][1]) + (e[ii][2] + e[ii][3]);
#pragma unroll
            for (int o = 8; o > 0; o >>= 1) r += __shfl_xor_sync(0xFFFFFFFFu, r, o);
            if (tx == 0) g_rpart[(bi + 2 * ty + ii) * 16 + bx] = r;
        }

        // col partials via smem (reduce over 32 ty values); reuses xs region
        float* red = SH;                       // [64][33]
        __syncthreads();
#pragma unroll
        for (int jj = 0; jj < 4; jj++)
            red[(4 * tx + jj) * 33 + ty] = e[0][jj] + e[1][jj];
        __syncthreads();
        if (tid < 64) {
            float c = 0.0f;
#pragma unroll
            for (int k = 0; k < 32; k++) c += red[tid * 33 + k];
            g_cpart[(bj + tid) * 16 + by] = c;
        }
    }

    grid_bar(0, true);                         // releaser resets g_ticket

    // ================= Phase 2: rinv / cinv (blocks 0-3) =================
    if (bid < 2) {
        int c = bid * 512 + tid;
        float t = 0.0f;
#pragma unroll
        for (int k = 0; k < 16; k++) t += g_cpart[c * 16 + k];
        g_cinv[c] = __fdividef(1.0f, t);
    } else if (bid < 4) {
        int r = (bid - 2) * 512 + tid;
        float t = 0.0f;
#pragma unroll
        for (int k = 0; k < 16; k++) t += g_rpart[r * 16 + k];
        g_rinv[r] = __fdividef(1.0f, t);
    }

    grid_bar(1, false);

    // ================= Phase 3: a = er+ec-er*ec; block partials =================
    float p1 = 0.0f, q2 = 0.0f;
    if (bid < 256) {
        const int row = bid * 4 + (tid >> 7);
        const int c0  = (tid & 127) * 8;
        const float ri = g_rinv[row];
        const float* dp = &g_d[row * 1024 + c0];
        const float* cp = &g_cinv[c0];
#pragma unroll
        for (int h = 0; h < 2; h++) {
            float4 d4 = *reinterpret_cast<const float4*>(dp + 4 * h);
            float4 c4 = *reinterpret_cast<const float4*>(cp + 4 * h);
            {
                float e = __expf(CSHIFT - d4.x);
                float er = e * ri, ec = e * c4.x;
                float a = er + ec - er * ec; p1 += a; q2 += a * d4.x;
            }
            {
                float e = __expf(CSHIFT - d4.y);
                float er = e * ri, ec = e * c4.y;
                float a = er + ec - er * ec; p1 += a; q2 += a * d4.y;
            }
            {
                float e = __expf(CSHIFT - d4.z);
                float er = e * ri, ec = e * c4.z;
                float a = er + ec - er * ec; p1 += a; q2 += a * d4.z;
            }
            {
                float e = __expf(CSHIFT - d4.w);
                float er = e * ri, ec = e * c4.w;
                float a = er + ec - er * ec; p1 += a; q2 += a * d4.w;
            }
        }
    }
    p1 = warp_sum(p1);
    q2 = warp_sum(q2);
    __syncthreads();
    if (lane == 0) { s_aux[w] = p1; s_aux[16 + w] = q2; }
    __syncthreads();
    if (tid == 0) {
        float a1 = 0.f, a2 = 0.f;
#pragma unroll
        for (int k = 0; k < 16; k++) { a1 += s_aux[k]; a2 += s_aux[16 + k]; }
        g_P1[bid] = a1;
        g_P2[bid] = -a2;                       // s = -d
        __threadfence();
        unsigned d = atomicAdd(&g_done, 1u);
        s_t = (d == NB - 1) ? 1u : 0u;
    }
    __syncthreads();

    // ================= Phase 4: last-done block finalizes =================
    if (s_t) {
        if (tid == 0) __threadfence();         // acquire all g_P writes
        __syncthreads();
        float v1 = (tid < NB) ? g_P1[tid] : 0.0f;
        float v2 = (tid < NB) ? g_P2[tid] : 0.0f;
        v1 = warp_sum(v1);
        v2 = warp_sum(v2);
        __syncthreads();
        if (lane == 0) { s_aux[w] = v1; s_aux[16 + w] = v2; }
        __syncthreads();
        if (tid == 0) {
            float S1 = 0.f, S2 = 0.f;
#pragma unroll
            for (int k = 0; k < 16; k++) { S1 += s_aux[k]; S2 += s_aux[16 + k]; }
            s_aux[32] = S2 / S1;
            g_done = 0;                        // reset for next replay
        }
        __syncthreads();
        if (tid < nout && nout <= 512)
            out[tid] = s_aux[32] * theta[tid] + beta[tid];
    }
}

// ---------------------------------------------------------------- launch
extern "C" void kernel_launch(void* const* d_in, const int* in_sizes, int n_in,
                              void* d_out, int out_size) {
    (void)n_in; (void)in_sizes;
    const float* zx    = (const float*)d_in[0];
    const float* zy    = (const float*)d_in[1];
    const float* theta = (const float*)d_in[2];
    const float* beta  = (const float*)d_in[3];
    float* out = (float*)d_out;

    k_all<<<NB, 512>>>(zx, zy, theta, beta, out, out_size);
}

// round 12
// speedup vs baseline: 1.3582x; 1.3582x over previous
#include <cuda_runtime.h>
#include <cuda_bf16.h>

#define NB 256
#define DIMK 128
#define TPX 68
#define CSHIFT 100.0f

// ---- scratch globals (allocation-free; all state self-resets across replays) ----
__device__ float    g_rpart[1024 * 16];    // row sumexp partials [row][bx]
__device__ float    g_cpart[1024 * 16];    // col sumexp partials [col][by]
__device__ float    g_P1[NB], g_P2[NB];
__device__ unsigned g_cnt[2];              // barrier arrivals (self-reset)
__device__ unsigned g_gen[2];              // barrier generations (monotonic)

// ---- FFMA-imm helpers (rt=1 on sm_103a vs rt=2 for FADD/FFMA-3reg) ----
// Constants perturbed by 1 ulp so ptxas cannot strength-reduce to FADD.
__device__ __forceinline__ float fdiff_(float x, float y) {
    float d;
    asm("fma.rn.f32 %0, %1, 0fBF800001, %2;" : "=f"(d) : "f"(y), "f"(x));
    return d;
}
__device__ __forceinline__ void facc_abs_(float& acc, float d) {
    asm("{\n\t"
        ".reg .f32 t;\n\t"
        "abs.f32 t, %1;\n\t"
        "fma.rn.f32 %0, t, 0f3F800001, %0;\n\t"
        "}"
        : "+f"(acc) : "f"(d));
}

__device__ __forceinline__ float warp_sum(float v) {
#pragma unroll
    for (int o = 16; o > 0; o >>= 1) v += __shfl_xor_sync(0xFFFFFFFFu, v, o);
    return v;
}

// grid barrier (identical to the R6 version that passed)
__device__ __forceinline__ void grid_bar(int i) {
    __syncthreads();
    if (threadIdx.x == 0) {
        volatile unsigned* genp = (volatile unsigned*)&g_gen[i];
        unsigned start = *genp;
        __threadfence();
        unsigned my = atomicAdd(&g_cnt[i], 1u);
        if (my == NB - 1) {
            g_cnt[i] = 0;
            __threadfence();
            atomicAdd(&g_gen[i], 1u);
        } else {
            while (*genp == start) { }
            __threadfence();
        }
    }
    __syncthreads();
}

// ---------------------------------------------------------------- the kernel
// 256 static blocks x 256 threads (2/SM, all resident); one 64x64 tile per
// block; 4x4 scalar micro-tile with FFMA-imm inner loop; everything register-
// resident across the 2 grid barriers.
__global__ __launch_bounds__(256, 2)
void k_all(const float* __restrict__ zx, const float* __restrict__ zy,
           const float* __restrict__ theta, const float* __restrict__ beta,
           float* __restrict__ out, int nout) {
    __shared__ float xs[64 * TPX];
    __shared__ float ys[64 * TPX];
    __shared__ float s_aux[40];

    const int tid  = threadIdx.x;
    const int lane = tid & 31, w = tid >> 5;
    const int tx   = tid & 15;                 // cols 4tx..4tx+3
    const int ty   = tid >> 4;                 // rows 4ty..4ty+3
    const int bid  = blockIdx.x;
    const int bx   = bid & 15, by = bid >> 4;
    const int bi   = by << 6, bj = bx << 6;

    // ================= Phase 1: L1 distances (FFMA-imm core) =================
    float acc[4][4];
#pragma unroll
    for (int i = 0; i < 4; i++)
#pragma unroll
        for (int j = 0; j < 4; j++) acc[i][j] = 0.0f;

    for (int kc = 0; kc < 2; kc++) {
        if (kc) __syncthreads();
#pragma unroll
        for (int l = tid; l < 1024; l += 256) {
            int r = l >> 4, dq = l & 15;
            int sw = (dq ^ ((r >> 2) & 15)) << 2;
            float4 vx = *reinterpret_cast<const float4*>(zx + (bi + r) * DIMK + kc * 64 + dq * 4);
            *reinterpret_cast<float4*>(&xs[r * TPX + sw]) = vx;
            float4 vy = *reinterpret_cast<const float4*>(zy + (bj + r) * DIMK + kc * 64 + dq * 4);
            *reinterpret_cast<float4*>(&ys[r * TPX + sw]) = vy;
        }
        __syncthreads();

#pragma unroll 4
        for (int dq = 0; dq < 16; dq++) {
            float4 av[4], bv[4];
            const int gx = (dq ^ ty) << 2;     // rows 4ty..4ty+3 share k = ty
            const int gy = (dq ^ tx) << 2;     // cols 4tx..4tx+3 share k = tx
#pragma unroll
            for (int ii = 0; ii < 4; ii++)
                av[ii] = *reinterpret_cast<const float4*>(&xs[(4 * ty + ii) * TPX + gx]);
#pragma unroll
            for (int jj = 0; jj < 4; jj++)
                bv[jj] = *reinterpret_cast<const float4*>(&ys[(4 * tx + jj) * TPX + gy]);
#pragma unroll
            for (int ii = 0; ii < 4; ii++)
#pragma unroll
                for (int jj = 0; jj < 4; jj++) {
                    facc_abs_(acc[ii][jj], fdiff_(av[ii].x, bv[jj].x));
                    facc_abs_(acc[ii][jj], fdiff_(av[ii].y, bv[jj].y));
                    facc_abs_(acc[ii][jj], fdiff_(av[ii].z, bv[jj].z));
                    facc_abs_(acc[ii][jj], fdiff_(av[ii].w, bv[jj].w));
                }
        }
    }

    // exp with constant shift (softmax shift-invariance; spread vs CSHIFT well
    // inside fp32 exp range) — e and acc stay in registers for phase 3.
    float e[4][4];
#pragma unroll
    for (int ii = 0; ii < 4; ii++)
#pragma unroll
        for (int jj = 0; jj < 4; jj++)
            e[ii][jj] = __expf(CSHIFT - acc[ii][jj]);

    // row partials (reduce over 16 tx lanes within half-warp)
#pragma unroll
    for (int ii = 0; ii < 4; ii++) {
        float r = (e[ii][0] + e[ii][1]) + (e[ii][2] + e[ii][3]);
#pragma unroll
        for (int o = 8; o > 0; o >>= 1) r += __shfl_xor_sync(0xFFFFFFFFu, r, o);
        if (tx == 0) g_rpart[(bi + 4 * ty + ii) * 16 + bx] = r;
    }

    // col partials via smem (reduce over 16 ty values); reuse xs
    {
        float* red = xs;                       // [64][17]
        __syncthreads();
#pragma unroll
        for (int jj = 0; jj < 4; jj++)
            red[(4 * tx + jj) * 17 + ty] = (e[0][jj] + e[1][jj]) + (e[2][jj] + e[3][jj]);
        __syncthreads();
        if (tid < 64) {
            float c = 0.0f;
#pragma unroll
            for (int k = 0; k < 16; k++) c += red[tid * 17 + k];
            g_cpart[(bj + tid) * 16 + by] = c;
        }
    }

    grid_bar(0);

    // ================= Phase 2: per-block rinv/cinv for own rows/cols =================
    float* rs = ys;                            // [64] 1/rowsum for rows bi..bi+63
    float* cs = ys + 64;                       // [64] 1/colsum for cols bj..bj+63
    if (tid < 64) {
        float t = 0.0f;
#pragma unroll
        for (int k = 0; k < 16; k++) t += g_rpart[(bi + tid) * 16 + k];
        rs[tid] = __fdividef(1.0f, t);
    } else if (tid < 128) {
        int c = tid - 64;
        float t = 0.0f;
#pragma unroll
        for (int k = 0; k < 16; k++) t += g_cpart[(bj + c) * 16 + k];
        cs[c] = __fdividef(1.0f, t);
    }
    __syncthreads();

    // ================= Phase 3: a = er+ec-er*ec from registers =================
    float csj[4];
#pragma unroll
    for (int jj = 0; jj < 4; jj++) csj[jj] = cs[4 * tx + jj];

    float p1 = 0.0f, p2 = 0.0f;
#pragma unroll
    for (int ii = 0; ii < 4; ii++) {
        float ri = rs[4 * ty + ii];
#pragma unroll
        for (int jj = 0; jj < 4; jj++) {
            float ev = e[ii][jj];
            float er = ev * ri;
            float ec = ev * csj[jj];
            float a = er + ec - er * ec;
            p1 += a;
            p2 -= a * acc[ii][jj];             // s = -dist
        }
    }
    p1 = warp_sum(p1);
    p2 = warp_sum(p2);
    __syncthreads();
    if (lane == 0) { s_aux[w] = p1; s_aux[16 + w] = p2; }
    __syncthreads();
    if (tid == 0) {
        float a1 = 0.f, a2 = 0.f;
#pragma unroll
        for (int k = 0; k < 8; k++) { a1 += s_aux[k]; a2 += s_aux[16 + k]; }
        g_P1[bid] = a1;
        g_P2[bid] = a2;
    }

    grid_bar(1);

    // ================= Phase 4: block 0 reduces + writes logits =================
    if (bid == 0) {
        float v1 = g_P1[tid];
        float v2 = g_P2[tid];
        v1 = warp_sum(v1);
        v2 = warp_sum(v2);
        __syncthreads();
        if (lane == 0) { s_aux[w] = v1; s_aux[16 + w] = v2; }
        __syncthreads();
        if (tid == 0) {
            float S1 = 0.f, S2 = 0.f;
#pragma unroll
            for (int k = 0; k < 8; k++) { S1 += s_aux[k]; S2 += s_aux[16 + k]; }
            s_aux[32] = S2 / S1;
        }
        __syncthreads();
        if (tid < nout && nout <= 256)
            out[tid] = s_aux[32] * theta[tid] + beta[tid];
    }
}

// ---------------------------------------------------------------- launch
extern "C" void kernel_launch(void* const* d_in, const int* in_sizes, int n_in,
                              void* d_out, int out_size) {
    (void)n_in; (void)in_sizes;
    const float* zx    = (const float*)d_in[0];
    const float* zy    = (const float*)d_in[1];
    const float* theta = (const float*)d_in[2];
    const float* beta  = (const float*)d_in[3];
    float* out = (float*)d_out;

    k_all<<<NB, 256>>>(zx, zy, theta, beta, out, out_size);
}

// round 14
// speedup vs baseline: 1.4252x; 1.0494x over previous
#include <cuda_runtime.h>
#include <cuda_bf16.h>

#define NB 256
#define DIMK 128
#define TPX 68
#define CSHIFT 100.0f

typedef unsigned long long ull;

// ---- scratch globals (allocation-free; all state self-resets across replays) ----
__device__ float    g_rpart[1024 * 16];    // row sumexp partials [row][bx]
__device__ float    g_cpart[1024 * 16];    // col sumexp partials [col][by]
__device__ float    g_P1[NB], g_P2[NB];
__device__ unsigned g_cnt[2];              // barrier arrivals (self-reset)
__device__ unsigned g_gen[2];              // barrier generations (monotonic)

#define NEG1_2 0xBF800000BF800000ULL

// packed diff: one instruction produces two (b - a) values; sign irrelevant
// because the consumer takes |.|.
__device__ __forceinline__ ull fma2_(ull a, ull b) {
    ull d;
    asm("fma.rn.f32x2 %0, %1, %2, %3;" : "=l"(d) : "l"(a), "l"(NEG1_2), "l"(b));
    return d;
}

// rt=1 FFMA-imm accumulate with folded |src|; imm perturbed 1 ulp so ptxas
// cannot strength-reduce to rt=2 FADD.
__device__ __forceinline__ void facc_abs_(float& acc, float d) {
    asm("{\n\t"
        ".reg .f32 t;\n\t"
        "abs.f32 t, %1;\n\t"
        "fma.rn.f32 %0, t, 0f3F800001, %0;\n\t"
        "}"
        : "+f"(acc) : "f"(d));
}

// accumulate both halves of a packed diff pair (register-pair aliasing, no movs)
union pair_u { ull u; float2 f; };
__device__ __forceinline__ void acc2_(float& acc, ull d) {
    pair_u p; p.u = d;
    facc_abs_(acc, p.f.x);
    facc_abs_(acc, p.f.y);
}

__device__ __forceinline__ float warp_sum(float v) {
#pragma unroll
    for (int o = 16; o > 0; o >>= 1) v += __shfl_xor_sync(0xFFFFFFFFu, v, o);
    return v;
}

// grid barrier (identical to passing R12 version)
__device__ __forceinline__ void grid_bar(int i) {
    __syncthreads();
    if (threadIdx.x == 0) {
        volatile unsigned* genp = (volatile unsigned*)&g_gen[i];
        unsigned start = *genp;
        __threadfence();
        unsigned my = atomicAdd(&g_cnt[i], 1u);
        if (my == NB - 1) {
            g_cnt[i] = 0;
            __threadfence();
            atomicAdd(&g_gen[i], 1u);
        } else {
            while (*genp == start) { }
            __threadfence();
        }
    }
    __syncthreads();
}

// ---------------------------------------------------------------- the kernel
// 256 static blocks x 256 threads (2/SM, all resident); one 64x64 tile per
// block; 4x4 micro-tile; packed-diff + scalar FFMA-imm accumulate (1.5 instr/elem).
__global__ __launch_bounds__(256, 2)
void k_all(const float* __restrict__ zx, const float* __restrict__ zy,
           const float* __restrict__ theta, const float* __restrict__ beta,
           float* __restrict__ out, int nout) {
    __shared__ float xs[64 * TPX];
    __shared__ float ys[64 * TPX];
    __shared__ float s_aux[40];

    const int tid  = threadIdx.x;
    const int lane = tid & 31, w = tid >> 5;
    const int tx   = tid & 15;                 // cols 4tx..4tx+3
    const int ty   = tid >> 4;                 // rows 4ty..4ty+3
    const int bid  = blockIdx.x;
    const int bx   = bid & 15, by = bid >> 4;
    const int bi   = by << 6, bj = bx << 6;

    // ================= Phase 1: L1 distances =================
    float acc[4][4];
#pragma unroll
    for (int i = 0; i < 4; i++)
#pragma unroll
        for (int j = 0; j < 4; j++) acc[i][j] = 0.0f;

    for (int kc = 0; kc < 2; kc++) {
        if (kc) __syncthreads();
#pragma unroll
        for (int l = tid; l < 1024; l += 256) {
            int r = l >> 4, dq = l & 15;
            int sw = (dq ^ ((r >> 2) & 15)) << 2;
            float4 vx = *reinterpret_cast<const float4*>(zx + (bi + r) * DIMK + kc * 64 + dq * 4);
            *reinterpret_cast<float4*>(&xs[r * TPX + sw]) = vx;
            float4 vy = *reinterpret_cast<const float4*>(zy + (bj + r) * DIMK + kc * 64 + dq * 4);
            *reinterpret_cast<float4*>(&ys[r * TPX + sw]) = vy;
        }
        __syncthreads();

#pragma unroll 4
        for (int dq = 0; dq < 16; dq++) {
            ulonglong2 av[4], bv[4];
            const int gx = (dq ^ ty) << 2;     // rows 4ty..4ty+3 share k = ty
            const int gy = (dq ^ tx) << 2;     // cols 4tx..4tx+3 share k = tx
#pragma unroll
            for (int ii = 0; ii < 4; ii++)
                av[ii] = *reinterpret_cast<const ulonglong2*>(&xs[(4 * ty + ii) * TPX + gx]);
#pragma unroll
            for (int jj = 0; jj < 4; jj++)
                bv[jj] = *reinterpret_cast<const ulonglong2*>(&ys[(4 * tx + jj) * TPX + gy]);
#pragma unroll
            for (int ii = 0; ii < 4; ii++)
#pragma unroll
                for (int jj = 0; jj < 4; jj++) {
                    acc2_(acc[ii][jj], fma2_(av[ii].x, bv[jj].x));
                    acc2_(acc[ii][jj], fma2_(av[ii].y, bv[jj].y));
                }
        }
    }

    // exp with constant shift — e and acc stay register-resident for phase 3.
    float e[4][4];
#pragma unroll
    for (int ii = 0; ii < 4; ii++)
#pragma unroll
        for (int jj = 0; jj < 4; jj++)
            e[ii][jj] = __expf(CSHIFT - acc[ii][jj]);

    // row partials (reduce over 16 tx lanes within half-warp)
#pragma unroll
    for (int ii = 0; ii < 4; ii++) {
        float r = (e[ii][0] + e[ii][1]) + (e[ii][2] + e[ii][3]);
#pragma unroll
        for (int o = 8; o > 0; o >>= 1) r += __shfl_xor_sync(0xFFFFFFFFu, r, o);
        if (tx == 0) g_rpart[(bi + 4 * ty + ii) * 16 + bx] = r;
    }

    // col partials via smem (reduce over 16 ty values); reuse xs
    {
        float* red = xs;                       // [64][17]
        __syncthreads();
#pragma unroll
        for (int jj = 0; jj < 4; jj++)
            red[(4 * tx + jj) * 17 + ty] = (e[0][jj] + e[1][jj]) + (e[2][jj] + e[3][jj]);
        __syncthreads();
        if (tid < 64) {
            float c = 0.0f;
#pragma unroll
            for (int k = 0; k < 16; k++) c += red[tid * 17 + k];
            g_cpart[(bj + tid) * 16 + by] = c;
        }
    }

    grid_bar(0);

    // ================= Phase 2: per-block rinv/cinv for own rows/cols =================
    float* rs = ys;                            // [64] 1/rowsum for rows bi..bi+63
    float* cs = ys + 64;                       // [64] 1/colsum for cols bj..bj+63
    if (tid < 64) {
        float t = 0.0f;
#pragma unroll
        for (int k = 0; k < 16; k++) t += g_rpart[(bi + tid) * 16 + k];
        rs[tid] = __fdividef(1.0f, t);
    } else if (tid < 128) {
        int c = tid - 64;
        float t = 0.0f;
#pragma unroll
        for (int k = 0; k < 16; k++) t += g_cpart[(bj + c) * 16 + k];
        cs[c] = __fdividef(1.0f, t);
    }
    __syncthreads();

    // ================= Phase 3: a = er+ec-er*ec from registers =================
    float csj[4];
#pragma unroll
    for (int jj = 0; jj < 4; jj++) csj[jj] = cs[4 * tx + jj];

    float p1 = 0.0f, p2 = 0.0f;
#pragma unroll
    for (int ii = 0; ii < 4; ii++) {
        float ri = rs[4 * ty + ii];
#pragma unroll
        for (int jj = 0; jj < 4; jj++) {
            float ev = e[ii][jj];
            float er = ev * ri;
            float ec = ev * csj[jj];
            float a = er + ec - er * ec;
            p1 += a;
            p2 -= a * acc[ii][jj];             // s = -dist
        }
    }
    p1 = warp_sum(p1);
    p2 = warp_sum(p2);
    __syncthreads();
    if (lane == 0) { s_aux[w] = p1; s_aux[16 + w] = p2; }
    __syncthreads();
    if (tid == 0) {
        float a1 = 0.f, a2 = 0.f;
#pragma unroll
        for (int k = 0; k < 8; k++) { a1 += s_aux[k]; a2 += s_aux[16 + k]; }
        g_P1[bid] = a1;
        g_P2[bid] = a2;
    }

    grid_bar(1);

    // ================= Phase 4: block 0 reduces + writes logits =================
    if (bid == 0) {
        float v1 = g_P1[tid];
        float v2 = g_P2[tid];
        v1 = warp_sum(v1);
        v2 = warp_sum(v2);
        __syncthreads();
        if (lane == 0) { s_aux[w] = v1; s_aux[16 + w] = v2; }
        __syncthreads();
        if (tid == 0) {
            float S1 = 0.f, S2 = 0.f;
#pragma unroll
            for (int k = 0; k < 8; k++) { S1 += s_aux[k]; S2 += s_aux[16 + k]; }
            s_aux[32] = S2 / S1;
        }
        __syncthreads();
        if (tid < nout && nout <= 256)
            out[tid] = s_aux[32] * theta[tid] + beta[tid];
    }
}

// ---------------------------------------------------------------- launch
extern "C" void kernel_launch(void* const* d_in, const int* in_sizes, int n_in,
                              void* d_out, int out_size) {
    (void)n_in; (void)in_sizes;
    const float* zx    = (const float*)d_in[0];
    const float* zy    = (const float*)d_in[1];
    const float* theta = (const float*)d_in[2];
    const float* beta  = (const float*)d_in[3];
    float* out = (float*)d_out;

    k_all<<<NB, 256>>>(zx, zy, theta, beta, out, out_size);
}